// round 1
// baseline (speedup 1.0000x reference)
#include <cuda_runtime.h>
#include <math_constants.h>

// Problem: N = 4096 mention-ranking loss.
// Per-row collapse:
//   bestM_i = max over masked entries of scores[i][:]  (lower tril from ana_scores, diag from eps)
//   maxU_i  = max over UNmasked strict-lower entries of ana row
//   row_cost = mask_ii>0 ? lc[0] : lc[1]
//   loss_i = max(0,
//                row_cost * (1 + maxU_i - bestM_i),          // -inf-safe if no unmasked
//                (1 - mask_ii) * fnc * (1 + eps_i - bestM_i))
// One streaming pass over mask lower triangle + ana_scores. No NxN matrix.

#define NMENT 4096
#define BLOCK 256

__global__ __launch_bounds__(BLOCK)
void mention_loss_kernel(const float* __restrict__ eps_scores,
                         const float* __restrict__ ana_scores,
                         const float* __restrict__ mask,
                         const float* __restrict__ link_costs,
                         const float* __restrict__ false_new_cost,
                         float* __restrict__ out)
{
    // Longest rows first for wave balance.
    const int row = NMENT - 1 - (int)blockIdx.x;
    const int tid = (int)threadIdx.x;

    const float* __restrict__ mrow = mask + (size_t)row * NMENT;
    const long long abase = ((long long)row * (row - 1)) >> 1;
    const float* __restrict__ arow = ana_scores + abase;

    float bestM = -CUDART_INF_F;
    float maxU  = -CUDART_INF_F;

    // Unrolled strided streaming pass over j in [0, row)
    int j = tid;
    #pragma unroll 4
    for (; j + 3 * BLOCK < row; j += 4 * BLOCK) {
        #pragma unroll
        for (int u = 0; u < 4; ++u) {
            float m = __ldg(mrow + j + u * BLOCK);
            float s = __ldg(arow + j + u * BLOCK);
            bool masked = (m > 0.5f);
            bestM = fmaxf(bestM, masked ? s : -CUDART_INF_F);
            maxU  = fmaxf(maxU,  masked ? -CUDART_INF_F : s);
        }
    }
    for (; j < row; j += BLOCK) {
        float m = __ldg(mrow + j);
        float s = __ldg(arow + j);
        bool masked = (m > 0.5f);
        bestM = fmaxf(bestM, masked ? s : -CUDART_INF_F);
        maxU  = fmaxf(maxU,  masked ? -CUDART_INF_F : s);
    }

    // Block reduction of (bestM, maxU)
    __shared__ float sM[BLOCK / 32];
    __shared__ float sU[BLOCK / 32];

    #pragma unroll
    for (int off = 16; off > 0; off >>= 1) {
        bestM = fmaxf(bestM, __shfl_xor_sync(0xffffffffu, bestM, off));
        maxU  = fmaxf(maxU,  __shfl_xor_sync(0xffffffffu, maxU,  off));
    }
    const int warp = tid >> 5;
    const int lane = tid & 31;
    if (lane == 0) { sM[warp] = bestM; sU[warp] = maxU; }
    __syncthreads();

    if (warp == 0) {
        bestM = (lane < BLOCK / 32) ? sM[lane] : -CUDART_INF_F;
        maxU  = (lane < BLOCK / 32) ? sU[lane] : -CUDART_INF_F;
        #pragma unroll
        for (int off = 4; off > 0; off >>= 1) {
            bestM = fmaxf(bestM, __shfl_xor_sync(0xffffffffu, bestM, off));
            maxU  = fmaxf(maxU,  __shfl_xor_sync(0xffffffffu, maxU,  off));
        }
        if (lane == 0) {
            const float nonana = __ldg(mrow + row);     // mask diagonal
            const float e      = __ldg(eps_scores + row);
            if (nonana > 0.5f) bestM = fmaxf(bestM, e);

            const float lc0 = __ldg(link_costs + 0);    // false_link
            const float lc1 = __ldg(link_costs + 1);    // wrong_link
            const float fnc = __ldg(false_new_cost);

            const float row_cost = nonana * lc0 + (1.0f - nonana) * lc1;

            float loss = 0.0f;
            // maxU == -inf  ->  row_cost * (-inf) = -inf -> dominated by 0. Branchless-safe.
            loss = fmaxf(loss, row_cost * (1.0f + maxU - bestM));
            const float dcost = (1.0f - nonana) * fnc;
            loss = fmaxf(loss, dcost * (1.0f + e - bestM));

            out[row] = loss;
        }
    }
}

extern "C" void kernel_launch(void* const* d_in, const int* in_sizes, int n_in,
                              void* d_out, int out_size)
{
    const float* eps  = (const float*)d_in[0];
    const float* ana  = (const float*)d_in[1];
    const float* mask = (const float*)d_in[2];
    const float* lc   = (const float*)d_in[3];
    const float* fnc  = (const float*)d_in[4];
    float* out = (float*)d_out;

    mention_loss_kernel<<<NMENT, BLOCK>>>(eps, ana, mask, lc, fnc, out);
}